// round 6
// baseline (speedup 1.0000x reference)
#include <cuda_runtime.h>
#include <float.h>
#include <math.h>

#define H 4096
#define V 32000
#define G (4 * H)
#define STEPS 20

// Sequential decode state lives in device globals (no allocation allowed).
__device__ float g_h[H];
__device__ float g_c[H];
__device__ float g_gates[G];
__device__ int   g_tok;

// ---------------------------------------------------------------------------
// init: h0 = noise + image_features, c0 = 0, tok0 = START_TOKEN (0)
// ---------------------------------------------------------------------------
__global__ void init_kernel(const float* __restrict__ imgf,
                            const float* __restrict__ noise) {
    int i = blockIdx.x * blockDim.x + threadIdx.x;
    if (i < H) {
        g_h[i] = imgf[i] + noise[i];
        g_c[i] = 0.0f;
    }
    if (i == 0) g_tok = 0;
}

// ---------------------------------------------------------------------------
// block-wide sum reduce, 128 threads (4 warps). Result valid in thread 0.
// ---------------------------------------------------------------------------
__device__ __forceinline__ float block_reduce_sum_128(float v) {
    __shared__ float s[4];
    int lane = threadIdx.x & 31;
    int w    = threadIdx.x >> 5;
    #pragma unroll
    for (int o = 16; o > 0; o >>= 1)
        v += __shfl_down_sync(0xffffffffu, v, o);
    if (lane == 0) s[w] = v;
    __syncthreads();
    if (w == 0) {
        v = (lane < 4) ? s[lane] : 0.0f;
        #pragma unroll
        for (int o = 2; o > 0; o >>= 1)
            v += __shfl_down_sync(0xffffffffu, v, o);
    }
    return v;
}

// ---------------------------------------------------------------------------
// gates[row] = W_ih[row,:] . embedding[tok] + b_ih[row]
//            + W_hh[row,:] . h             + b_hh[row]
// One block per row (16384 blocks x 128 threads). Streams 32 KB/row.
// ---------------------------------------------------------------------------
__global__ void __launch_bounds__(128)
gates_kernel(const float* __restrict__ emb,
             const float* __restrict__ Wih,
             const float* __restrict__ Whh,
             const float* __restrict__ bih,
             const float* __restrict__ bhh) {
    int row = blockIdx.x;
    int t   = threadIdx.x;

    const float4* x  = (const float4*)(emb + (size_t)g_tok * H);
    const float4* hh = (const float4*)g_h;
    const float4* wi = (const float4*)(Wih + (size_t)row * H);
    const float4* wh = (const float4*)(Whh + (size_t)row * H);

    float acc = 0.0f;
    #pragma unroll
    for (int i = 0; i < H / 4 / 128; i++) {   // 8 iterations
        int c = t + i * 128;
        float4 a  = wi[c];
        float4 b  = x[c];
        acc += a.x * b.x + a.y * b.y + a.z * b.z + a.w * b.w;
        float4 a2 = wh[c];
        float4 b2 = hh[c];
        acc += a2.x * b2.x + a2.y * b2.y + a2.z * b2.z + a2.w * b2.w;
    }
    float s = block_reduce_sum_128(acc);
    if (t == 0) g_gates[row] = s + bih[row] + bhh[row];
}

// ---------------------------------------------------------------------------
// LSTM cell update (torch gate order i, f, g, o):
//   c = sigmoid(f)*c + sigmoid(i)*tanh(g);  h = sigmoid(o)*tanh(c)
// ---------------------------------------------------------------------------
__device__ __forceinline__ float sigmoidf_(float x) {
    return 1.0f / (1.0f + expf(-x));
}

__global__ void cell_kernel() {
    int j = blockIdx.x * blockDim.x + threadIdx.x;
    if (j >= H) return;
    float ig = g_gates[j];
    float fg = g_gates[H + j];
    float gg = g_gates[2 * H + j];
    float og = g_gates[3 * H + j];
    float c = sigmoidf_(fg) * g_c[j] + sigmoidf_(ig) * tanhf(gg);
    g_c[j] = c;
    g_h[j] = sigmoidf_(og) * tanhf(c);
}

// ---------------------------------------------------------------------------
// logits[row] = W_out[row,:] . h + b_out[row]   (32000 blocks x 128 threads)
// ---------------------------------------------------------------------------
__global__ void __launch_bounds__(128)
logits_kernel(const float* __restrict__ Wout,
              const float* __restrict__ bout,
              float* __restrict__ out) {
    int row = blockIdx.x;
    int t   = threadIdx.x;

    const float4* hh = (const float4*)g_h;
    const float4* w  = (const float4*)(Wout + (size_t)row * H);

    float acc = 0.0f;
    #pragma unroll
    for (int i = 0; i < H / 4 / 128; i++) {   // 8 iterations
        int c = t + i * 128;
        float4 a = w[c];
        float4 b = hh[c];
        acc += a.x * b.x + a.y * b.y + a.z * b.z + a.w * b.w;
    }
    float s = block_reduce_sum_128(acc);
    if (t == 0) out[row] = s + bout[row];
}

// ---------------------------------------------------------------------------
// Greedy argmax over 32000 logits -> g_tok. First-max (lowest index) wins,
// matching jnp.argmax semantics.
// ---------------------------------------------------------------------------
__global__ void argmax_kernel(const float* __restrict__ logits) {
    __shared__ float sv[32];
    __shared__ int   si[32];
    int t    = threadIdx.x;
    int lane = t & 31;
    int w    = t >> 5;

    float best = -FLT_MAX;
    int   bi   = 0x7fffffff;
    for (int i = t; i < V; i += blockDim.x) {
        float v = logits[i];
        if (v > best) { best = v; bi = i; }   // strict > keeps earliest index
    }
    #pragma unroll
    for (int o = 16; o > 0; o >>= 1) {
        float ov = __shfl_down_sync(0xffffffffu, best, o);
        int   oi = __shfl_down_sync(0xffffffffu, bi, o);
        if (ov > best || (ov == best && oi < bi)) { best = ov; bi = oi; }
    }
    if (lane == 0) { sv[w] = best; si[w] = bi; }
    __syncthreads();
    if (w == 0) {
        int nw = blockDim.x >> 5;
        best = (lane < nw) ? sv[lane] : -FLT_MAX;
        bi   = (lane < nw) ? si[lane] : 0x7fffffff;
        #pragma unroll
        for (int o = 16; o > 0; o >>= 1) {
            float ov = __shfl_down_sync(0xffffffffu, best, o);
            int   oi = __shfl_down_sync(0xffffffffu, bi, o);
            if (ov > best || (ov == best && oi < bi)) { best = ov; bi = oi; }
        }
        if (lane == 0) g_tok = bi;
    }
}

// ---------------------------------------------------------------------------
// kernel_launch: 1 init + 20 x (gates, cell, logits, argmax) = 81 launches,
// all plain kernel launches on the capture stream (graph-capturable,
// allocation-free). Sequential dependency carried by stream order.
// ---------------------------------------------------------------------------
extern "C" void kernel_launch(void* const* d_in, const int* in_sizes, int n_in,
                              void* d_out, int out_size) {
    const float* imgf  = (const float*)d_in[0];  // image_features [1,1,4096]
    const float* noise = (const float*)d_in[1];  // noise          [1,1,4096]
    const float* emb   = (const float*)d_in[2];  // embedding      [32000,4096]
    const float* Wih   = (const float*)d_in[3];  // W_ih           [16384,4096]
    const float* Whh   = (const float*)d_in[4];  // W_hh           [16384,4096]
    const float* bih   = (const float*)d_in[5];  // b_ih           [16384]
    const float* bhh   = (const float*)d_in[6];  // b_hh           [16384]
    const float* Wout  = (const float*)d_in[7];  // W_out          [32000,4096]
    const float* bout  = (const float*)d_in[8];  // b_out          [32000]
    float* out = (float*)d_out;                  // [20, 32000] fp32 logits

    init_kernel<<<(H + 255) / 256, 256>>>(imgf, noise);
    for (int s = 0; s < STEPS; s++) {
        gates_kernel<<<G, 128>>>(emb, Wih, Whh, bih, bhh);
        cell_kernel<<<H / 256, 256>>>();
        logits_kernel<<<V, 128>>>(Wout, bout, out + (size_t)s * V);
        argmax_kernel<<<1, 1024>>>(out + (size_t)s * V);
    }
}

// round 8
// speedup vs baseline: 1.3864x; 1.3864x over previous
#include <cuda_runtime.h>
#include <cuda_fp16.h>
#include <float.h>
#include <math.h>

#define H 4096
#define V 32000
#define G (4 * H)
#define STEPS 20

// Sequential decode state lives in device globals (no allocation allowed).
__device__ float g_h[H];
__device__ float g_c[H];
__device__ float g_gates[G];
__device__ int   g_tok;

// fp16 weight cache (static device scratch: 128 + 128 + 250 MB).
__device__ __half g_Wih[(size_t)G * H];
__device__ __half g_Whh[(size_t)G * H];
__device__ __half g_Wout[(size_t)V * H];

// ---------------------------------------------------------------------------
// fp32 -> fp16 conversion (vectorized: float4 in, half4 out). One kernel per
// weight matrix; dst is a __device__ global referenced from device code.
// ---------------------------------------------------------------------------
__device__ __forceinline__ uint2 f4_to_h4(float4 v) {
    __half2 lo = __floats2half2_rn(v.x, v.y);
    __half2 hi = __floats2half2_rn(v.z, v.w);
    uint2 o;
    o.x = *reinterpret_cast<unsigned*>(&lo);
    o.y = *reinterpret_cast<unsigned*>(&hi);
    return o;
}

__global__ void convert_wih(const float4* __restrict__ src) {
    int i = blockIdx.x * blockDim.x + threadIdx.x;   // G*H/4 = 16,777,216
    ((uint2*)g_Wih)[i] = f4_to_h4(src[i]);
}
__global__ void convert_whh(const float4* __restrict__ src) {
    int i = blockIdx.x * blockDim.x + threadIdx.x;
    ((uint2*)g_Whh)[i] = f4_to_h4(src[i]);
}
__global__ void convert_wout(const float4* __restrict__ src) {
    int i = blockIdx.x * blockDim.x + threadIdx.x;   // V*H/4 = 32,768,000
    ((uint2*)g_Wout)[i] = f4_to_h4(src[i]);
}

// ---------------------------------------------------------------------------
// init: h0 = noise + image_features, c0 = 0, tok0 = START_TOKEN (0)
// ---------------------------------------------------------------------------
__global__ void init_kernel(const float* __restrict__ imgf,
                            const float* __restrict__ noise) {
    int i = blockIdx.x * blockDim.x + threadIdx.x;
    if (i < H) {
        g_h[i] = imgf[i] + noise[i];
        g_c[i] = 0.0f;
    }
    if (i == 0) g_tok = 0;
}

// ---------------------------------------------------------------------------
// block-wide sum reduce, 128 threads (4 warps). Result valid in thread 0.
// ---------------------------------------------------------------------------
__device__ __forceinline__ float block_reduce_sum_128(float v) {
    __shared__ float s[4];
    int lane = threadIdx.x & 31;
    int w    = threadIdx.x >> 5;
    #pragma unroll
    for (int o = 16; o > 0; o >>= 1)
        v += __shfl_down_sync(0xffffffffu, v, o);
    if (lane == 0) s[w] = v;
    __syncthreads();
    if (w == 0) {
        v = (lane < 4) ? s[lane] : 0.0f;
        #pragma unroll
        for (int o = 2; o > 0; o >>= 1)
            v += __shfl_down_sync(0xffffffffu, v, o);
    }
    return v;
}

// 8 fp16 weights (one uint4) dotted with 8 fp32 activations, fp32 accumulate.
__device__ __forceinline__ float dot8(uint4 a, float4 v0, float4 v1) {
    const __half2* p = reinterpret_cast<const __half2*>(&a);
    float2 f0 = __half22float2(p[0]);
    float2 f1 = __half22float2(p[1]);
    float2 f2 = __half22float2(p[2]);
    float2 f3 = __half22float2(p[3]);
    return f0.x * v0.x + f0.y * v0.y + f1.x * v0.z + f1.y * v0.w
         + f2.x * v1.x + f2.y * v1.y + f3.x * v1.z + f3.y * v1.w;
}

// ---------------------------------------------------------------------------
// gates[row] = Wih_h[row,:] . emb[tok] + b_ih[row] + Whh_h[row,:] . h + b_hh[row]
// One block per row (16384 blocks x 128 threads). Streams 16 KB/row (fp16).
// ---------------------------------------------------------------------------
__global__ void __launch_bounds__(128)
gates_kernel(const float* __restrict__ emb,
             const float* __restrict__ bih,
             const float* __restrict__ bhh) {
    int row = blockIdx.x;
    int t   = threadIdx.x;

    const float4* x  = (const float4*)(emb + (size_t)g_tok * H);
    const float4* hh = (const float4*)g_h;
    const uint4*  wi = (const uint4*)(g_Wih + (size_t)row * H);
    const uint4*  wh = (const uint4*)(g_Whh + (size_t)row * H);

    float acc = 0.0f;
    #pragma unroll
    for (int i = 0; i < H / 8 / 128; i++) {   // 4 iterations, 8 elems each
        int c = t + i * 128;
        uint4  a  = wi[c];
        uint4  b  = wh[c];
        float4 x0 = x[2 * c], x1 = x[2 * c + 1];
        float4 h0 = hh[2 * c], h1 = hh[2 * c + 1];
        acc += dot8(a, x0, x1);
        acc += dot8(b, h0, h1);
    }
    float s = block_reduce_sum_128(acc);
    if (t == 0) g_gates[row] = s + bih[row] + bhh[row];
}

// ---------------------------------------------------------------------------
// LSTM cell update (torch gate order i, f, g, o)
// ---------------------------------------------------------------------------
__device__ __forceinline__ float sigmoidf_(float x) {
    return 1.0f / (1.0f + expf(-x));
}

__global__ void cell_kernel() {
    int j = blockIdx.x * blockDim.x + threadIdx.x;
    if (j >= H) return;
    float ig = g_gates[j];
    float fg = g_gates[H + j];
    float gg = g_gates[2 * H + j];
    float og = g_gates[3 * H + j];
    float c = sigmoidf_(fg) * g_c[j] + sigmoidf_(ig) * tanhf(gg);
    g_c[j] = c;
    g_h[j] = sigmoidf_(og) * tanhf(c);
}

// ---------------------------------------------------------------------------
// logits[row] = Wout_h[row,:] . h + b_out[row]   (32000 blocks x 128 threads)
// ---------------------------------------------------------------------------
__global__ void __launch_bounds__(128)
logits_kernel(const float* __restrict__ bout,
              float* __restrict__ out) {
    int row = blockIdx.x;
    int t   = threadIdx.x;

    const float4* hh = (const float4*)g_h;
    const uint4*  w  = (const uint4*)(g_Wout + (size_t)row * H);

    float acc = 0.0f;
    #pragma unroll
    for (int i = 0; i < H / 8 / 128; i++) {   // 4 iterations
        int c = t + i * 128;
        uint4  a  = w[c];
        float4 h0 = hh[2 * c], h1 = hh[2 * c + 1];
        acc += dot8(a, h0, h1);
    }
    float s = block_reduce_sum_128(acc);
    if (t == 0) out[row] = s + bout[row];
}

// ---------------------------------------------------------------------------
// Greedy argmax over 32000 logits -> g_tok. First-max (lowest index) wins.
// ---------------------------------------------------------------------------
__global__ void argmax_kernel(const float* __restrict__ logits) {
    __shared__ float sv[32];
    __shared__ int   si[32];
    int t    = threadIdx.x;
    int lane = t & 31;
    int w    = t >> 5;

    float best = -FLT_MAX;
    int   bi   = 0x7fffffff;
    for (int i = t; i < V; i += blockDim.x) {
        float v = logits[i];
        if (v > best) { best = v; bi = i; }   // strict > keeps earliest index
    }
    #pragma unroll
    for (int o = 16; o > 0; o >>= 1) {
        float ov = __shfl_down_sync(0xffffffffu, best, o);
        int   oi = __shfl_down_sync(0xffffffffu, bi, o);
        if (ov > best || (ov == best && oi < bi)) { best = ov; bi = oi; }
    }
    if (lane == 0) { sv[w] = best; si[w] = bi; }
    __syncthreads();
    if (w == 0) {
        int nw = blockDim.x >> 5;
        best = (lane < nw) ? sv[lane] : -FLT_MAX;
        bi   = (lane < nw) ? si[lane] : 0x7fffffff;
        #pragma unroll
        for (int o = 16; o > 0; o >>= 1) {
            float ov = __shfl_down_sync(0xffffffffu, best, o);
            int   oi = __shfl_down_sync(0xffffffffu, bi, o);
            if (ov > best || (ov == best && oi < bi)) { best = ov; bi = oi; }
        }
        if (lane == 0) g_tok = bi;
    }
}

// ---------------------------------------------------------------------------
// kernel_launch: 3 convert + 1 init + 20 x (gates, cell, logits, argmax).
// All plain launches on the capture stream (graph-capturable, allocation-free).
// ---------------------------------------------------------------------------
extern "C" void kernel_launch(void* const* d_in, const int* in_sizes, int n_in,
                              void* d_out, int out_size) {
    const float* imgf  = (const float*)d_in[0];  // image_features [1,1,4096]
    const float* noise = (const float*)d_in[1];  // noise          [1,1,4096]
    const float* emb   = (const float*)d_in[2];  // embedding      [32000,4096]
    const float* Wih   = (const float*)d_in[3];  // W_ih           [16384,4096]
    const float* Whh   = (const float*)d_in[4];  // W_hh           [16384,4096]
    const float* bih   = (const float*)d_in[5];  // b_ih           [16384]
    const float* bhh   = (const float*)d_in[6];  // b_hh           [16384]
    const float* Wout  = (const float*)d_in[7];  // W_out          [32000,4096]
    const float* bout  = (const float*)d_in[8];  // b_out          [32000]
    float* out = (float*)d_out;                  // [20, 32000] fp32 logits

    const int nW  = G * H / 4;   // 16,777,216 float4s (exact multiple of 256)
    const int nWo = V * H / 4;   // 32,768,000 float4s (exact multiple of 256)
    convert_wih<<<nW / 256, 256>>>((const float4*)Wih);
    convert_whh<<<nW / 256, 256>>>((const float4*)Whh);
    convert_wout<<<nWo / 256, 256>>>((const float4*)Wout);

    init_kernel<<<(H + 255) / 256, 256>>>(imgf, noise);
    for (int s = 0; s < STEPS; s++) {
        gates_kernel<<<G, 128>>>(emb, bih, bhh);
        cell_kernel<<<H / 256, 256>>>();
        logits_kernel<<<V, 128>>>(bout, out + (size_t)s * V);
        argmax_kernel<<<1, 1024>>>(out + (size_t)s * V);
    }
}